// round 1
// baseline (speedup 1.0000x reference)
#include <cuda_runtime.h>

#define NN 100000
#define NE 3000000
#define THIRD (NE/3)
#define NG 256
#define FIN 64
#define NH 32

// ---- scratch (no allocations allowed) ----
__device__ float d_sp[3];
__device__ float d_M[FIN * NH];
__device__ float d_bvec[NH];
__device__ float d_ew[NE];
__device__ float d_dinv[NN];        // deg, then rsqrt(deg) in place
__device__ float d_g[NN * NH];      // dinv[n] * hW[n]
__device__ float d_acc[NN * NH];    // edge-sum accumulator
__device__ float d_pooled[NG * NH];

// ---- tiny precompute: softmax(msg_weights), fused matrix M = [gcn_W[0]; emb_W @ gcn_W[1:]], bvec ----
__global__ void k_prep(const float* __restrict__ mw, const float* __restrict__ embW,
                       const float* __restrict__ embB, const float* __restrict__ gcnW) {
    int tid = threadIdx.x;
    if (tid == 0) {
        float m = fmaxf(mw[0], fmaxf(mw[1], mw[2]));
        float e0 = expf(mw[0] - m), e1 = expf(mw[1] - m), e2 = expf(mw[2] - m);
        float inv = 1.0f / (e0 + e1 + e2);
        d_sp[0] = e0 * inv; d_sp[1] = e1 * inv; d_sp[2] = e2 * inv;
    }
    for (int idx = tid; idx < FIN * NH; idx += blockDim.x) {
        int i = idx / NH, k = idx % NH;
        float v;
        if (i == 0) {
            v = gcnW[k];
        } else {
            v = 0.f;
            for (int c = 0; c < 63; c++)
                v += embW[(i - 1) * 63 + c] * gcnW[(1 + c) * NH + k];
        }
        d_M[idx] = v;
    }
    if (tid < NH) {
        float v = 0.f;
        for (int c = 0; c < 63; c++) v += embB[c] * gcnW[(1 + c) * NH + tid];
        d_bvec[tid] = v;
    }
}

// ---- scatter edge weights: every edge covered by exactly one mask ----
__global__ void k_ew(const int* __restrict__ km, const int* __restrict__ um,
                     const int* __restrict__ om) {
    int t = blockIdx.x * blockDim.x + threadIdx.x;
    if (t < THIRD)          d_ew[km[t]] = d_sp[0];
    else if (t < 2 * THIRD) d_ew[um[t - THIRD]] = d_sp[1];
    else if (t < NE)        d_ew[om[t - 2 * THIRD]] = d_sp[2];
}

__global__ void k_deg_init() {
    int n = blockIdx.x * blockDim.x + threadIdx.x;
    if (n < NN) d_dinv[n] = 1.0f;  // self-loop weight
}

__global__ void k_deg(const int* __restrict__ ei) {
    int e = blockIdx.x * blockDim.x + threadIdx.x;
    if (e < NE) atomicAdd(&d_dinv[__ldg(&ei[NE + e])], __ldg(&d_ew[e]));
}

__global__ void k_dinv() {
    int n = blockIdx.x * blockDim.x + threadIdx.x;
    if (n < NN) {
        float d = d_dinv[n];
        d_dinv[n] = (d > 0.f) ? rsqrtf(d) : 0.f;
    }
}

// ---- g[n] = dinv[n] * (x[n] @ M + bvec); also zero acc and pooled ----
__global__ void k_g(const float* __restrict__ x) {
    __shared__ float4 Ms[FIN * NH / 4];
    __shared__ float Bs[NH];
    int tid = threadIdx.x;
    for (int i = tid; i < FIN * NH / 4; i += blockDim.x) Ms[i] = ((const float4*)d_M)[i];
    if (tid < NH) Bs[tid] = d_bvec[tid];
    __syncthreads();

    int n = blockIdx.x * blockDim.x + tid;
    if (n < NG * NH) d_pooled[n] = 0.f;
    if (n >= NN) return;

    float acc[NH];
#pragma unroll
    for (int k = 0; k < NH; k++) acc[k] = 0.f;

    const float4* xr = (const float4*)(x + (size_t)n * FIN);
#pragma unroll
    for (int i4 = 0; i4 < FIN / 4; i4++) {
        float4 xv = __ldg(&xr[i4]);
        float xs[4] = {xv.x, xv.y, xv.z, xv.w};
#pragma unroll
        for (int j = 0; j < 4; j++) {
            float xi = xs[j];
            int i = i4 * 4 + j;
#pragma unroll
            for (int k4 = 0; k4 < NH / 4; k4++) {
                float4 m = Ms[i * (NH / 4) + k4];
                acc[k4 * 4 + 0] = fmaf(xi, m.x, acc[k4 * 4 + 0]);
                acc[k4 * 4 + 1] = fmaf(xi, m.y, acc[k4 * 4 + 1]);
                acc[k4 * 4 + 2] = fmaf(xi, m.z, acc[k4 * 4 + 2]);
                acc[k4 * 4 + 3] = fmaf(xi, m.w, acc[k4 * 4 + 3]);
            }
        }
    }
    float di = d_dinv[n];
    float4* go = (float4*)(d_g + (size_t)n * NH);
    float4* ao = (float4*)(d_acc + (size_t)n * NH);
#pragma unroll
    for (int k4 = 0; k4 < NH / 4; k4++) {
        float4 o;
        o.x = di * (acc[k4 * 4 + 0] + Bs[k4 * 4 + 0]);
        o.y = di * (acc[k4 * 4 + 1] + Bs[k4 * 4 + 1]);
        o.z = di * (acc[k4 * 4 + 2] + Bs[k4 * 4 + 2]);
        o.w = di * (acc[k4 * 4 + 3] + Bs[k4 * 4 + 3]);
        go[k4] = o;
        ao[k4] = make_float4(0.f, 0.f, 0.f, 0.f);
    }
}

// ---- hot loop: one warp per edge (grid-stride), lane = feature ----
__global__ void k_edge(const int* __restrict__ ei) {
    int lane = threadIdx.x & 31;
    int warp = (blockIdx.x * blockDim.x + threadIdx.x) >> 5;
    int nwarps = (gridDim.x * blockDim.x) >> 5;
    for (int e = warp; e < NE; e += nwarps) {
        int r = __ldg(&ei[e]);
        int c = __ldg(&ei[NE + e]);
        float w = __ldg(&d_ew[e]);
        float val = w * __ldg(&d_g[(size_t)r * NH + lane]);
        atomicAdd(&d_acc[(size_t)c * NH + lane], val);
    }
}

// ---- fixup + relu + segment pool (batch sorted -> register accumulation per warp) ----
#define CHUNK 64
__global__ void k_pool(const int* __restrict__ batch, const float* __restrict__ gcnB) {
    int lane = threadIdx.x & 31;
    int warp = (blockIdx.x * blockDim.x + threadIdx.x) >> 5;
    int start = warp * CHUNK;
    if (start >= NN) return;
    int end = min(start + CHUNK, NN);
    float gb = __ldg(&gcnB[lane]);
    int cur = __ldg(&batch[start]);
    float accr = 0.f;
    for (int n = start; n < end; n++) {
        int b = __ldg(&batch[n]);
        if (b != cur) {
            atomicAdd(&d_pooled[cur * NH + lane], accr);
            accr = 0.f;
            cur = b;
        }
        float a = d_acc[(size_t)n * NH + lane] + d_g[(size_t)n * NH + lane];
        float v = fmaxf(fmaf(d_dinv[n], a, gb), 0.f);
        accr += v;
    }
    atomicAdd(&d_pooled[cur * NH + lane], accr);
}

// ---- head MLP: one thread per graph ----
__global__ void k_final(const float* __restrict__ fc1W, const float* __restrict__ fc1B,
                        const float* __restrict__ outW, const float* __restrict__ outB,
                        float* __restrict__ out) {
    __shared__ float W[NH * NH], b1[NH], wo[NH];
    int tid = threadIdx.x;
    for (int i = tid; i < NH * NH; i += blockDim.x) W[i] = fc1W[i];
    if (tid < NH) { b1[tid] = fc1B[tid]; wo[tid] = outW[tid]; }
    __syncthreads();
    if (tid >= NG) return;

    float p[NH];
    const float4* pr = (const float4*)(d_pooled + tid * NH);
#pragma unroll
    for (int k4 = 0; k4 < NH / 4; k4++) {
        float4 v = pr[k4];
        p[k4 * 4 + 0] = v.x; p[k4 * 4 + 1] = v.y;
        p[k4 * 4 + 2] = v.z; p[k4 * 4 + 3] = v.w;
    }
    float o = outB[0];
#pragma unroll
    for (int j = 0; j < NH; j++) {
        float z = b1[j];
#pragma unroll
        for (int i = 0; i < NH; i++) z = fmaf(p[i], W[i * NH + j], z);
        o = fmaf(fmaxf(z, 0.f), wo[j], o);
    }
    out[tid] = o;
}

extern "C" void kernel_launch(void* const* d_in, const int* in_sizes, int n_in,
                              void* d_out, int out_size) {
    const float* x    = (const float*)d_in[0];
    const int*   ei   = (const int*)d_in[1];
    const int*   bat  = (const int*)d_in[2];
    const int*   km   = (const int*)d_in[3];
    const int*   um   = (const int*)d_in[4];
    const int*   om   = (const int*)d_in[5];
    const float* mw   = (const float*)d_in[6];
    const float* embW = (const float*)d_in[7];
    const float* embB = (const float*)d_in[8];
    const float* gcnW = (const float*)d_in[9];
    const float* gcnB = (const float*)d_in[10];
    const float* fc1W = (const float*)d_in[11];
    const float* fc1B = (const float*)d_in[12];
    const float* outW = (const float*)d_in[13];
    const float* outB = (const float*)d_in[14];
    float* out = (float*)d_out;

    k_prep<<<1, 256>>>(mw, embW, embB, gcnW);
    k_ew<<<(NE + 255) / 256, 256>>>(km, um, om);
    k_deg_init<<<(NN + 255) / 256, 256>>>();
    k_deg<<<(NE + 255) / 256, 256>>>(ei);
    k_dinv<<<(NN + 255) / 256, 256>>>();
    k_g<<<(NN + 255) / 256, 256>>>(x);
    k_edge<<<2368, 256>>>(ei);
    int pool_warps = (NN + CHUNK - 1) / CHUNK;
    k_pool<<<(pool_warps + 7) / 8, 256>>>(bat, gcnB);
    k_final<<<1, 256>>>(fc1W, fc1B, outW, outB, out);
}

// round 2
// speedup vs baseline: 1.2201x; 1.2201x over previous
#include <cuda_runtime.h>

#define NN 100000
#define NE 3000000
#define THIRD (NE/3)
#define NG 256
#define FIN 64
#define NH 32

// ---- scratch (no allocations allowed) ----
__device__ float d_sp[3];
__device__ float d_M[FIN * NH];
__device__ float d_bvec[NH];
__device__ unsigned char d_code[NE];   // 0/1/2 -> which softmax weight
__device__ float d_dinv[NN];           // deg, then rsqrt(deg) in place
__device__ float d_g[NN * NH];         // dinv[n] * hW[n]
__device__ float d_acc[NN * NH];       // edge-sum accumulator
__device__ float d_pooled[NG * NH];

__device__ __forceinline__ void red_add_v4(float* addr, float a, float b, float c, float d) {
    asm volatile("red.global.add.v4.f32 [%0], {%1,%2,%3,%4};"
                 :: "l"(addr), "f"(a), "f"(b), "f"(c), "f"(d) : "memory");
}

// ---- tiny precompute: softmax(msg_weights), fused matrix M = [gcn_W[0]; emb_W @ gcn_W[1:]], bvec ----
__global__ void k_prep(const float* __restrict__ mw, const float* __restrict__ embW,
                       const float* __restrict__ embB, const float* __restrict__ gcnW) {
    int tid = threadIdx.x;
    if (tid == 0) {
        float m = fmaxf(mw[0], fmaxf(mw[1], mw[2]));
        float e0 = expf(mw[0] - m), e1 = expf(mw[1] - m), e2 = expf(mw[2] - m);
        float inv = 1.0f / (e0 + e1 + e2);
        d_sp[0] = e0 * inv; d_sp[1] = e1 * inv; d_sp[2] = e2 * inv;
    }
    for (int idx = tid; idx < FIN * NH; idx += blockDim.x) {
        int i = idx / NH, k = idx % NH;
        float v;
        if (i == 0) {
            v = gcnW[k];
        } else {
            v = 0.f;
            for (int c = 0; c < 63; c++)
                v += embW[(i - 1) * 63 + c] * gcnW[(1 + c) * NH + k];
        }
        d_M[idx] = v;
    }
    if (tid < NH) {
        float v = 0.f;
        for (int c = 0; c < 63; c++) v += embB[c] * gcnW[(1 + c) * NH + tid];
        d_bvec[tid] = v;
    }
}

// ---- scatter edge codes + init dinv to self-loop weight ----
__global__ void k_ew(const int* __restrict__ km, const int* __restrict__ um,
                     const int* __restrict__ om) {
    int t = blockIdx.x * blockDim.x + threadIdx.x;
    if (t < THIRD)          d_code[__ldg(&km[t])] = 0;
    else if (t < 2 * THIRD) d_code[__ldg(&um[t - THIRD])] = 1;
    else if (t < NE)        d_code[__ldg(&om[t - 2 * THIRD])] = 2;
    if (t < NN) d_dinv[t] = 1.0f;
}

// ---- degree accumulate: 4 edges per thread ----
__global__ void k_deg(const int* __restrict__ ei) {
    int t = blockIdx.x * blockDim.x + threadIdx.x;
    float s0 = d_sp[0], s1 = d_sp[1], s2 = d_sp[2];
    int e0 = t * 4;
    if (e0 + 3 < NE) {
        uchar4 cd = __ldg((const uchar4*)(d_code + e0));
        int4 col = __ldg((const int4*)(ei + NE + e0));
        unsigned char cs[4] = {cd.x, cd.y, cd.z, cd.w};
        int cols[4] = {col.x, col.y, col.z, col.w};
#pragma unroll
        for (int j = 0; j < 4; j++) {
            float w = cs[j] == 0 ? s0 : (cs[j] == 1 ? s1 : s2);
            atomicAdd(&d_dinv[cols[j]], w);
        }
    } else {
        for (int e = e0; e < NE; e++) {
            unsigned char cd = d_code[e];
            float w = cd == 0 ? s0 : (cd == 1 ? s1 : s2);
            atomicAdd(&d_dinv[__ldg(&ei[NE + e])], w);
        }
    }
}

// ---- g[n] = rsqrt(deg)[n] * (x[n] @ M + bvec); dinv finalized in-place; zero acc & pooled ----
__global__ void k_g(const float* __restrict__ x) {
    __shared__ float4 Ms[FIN * NH / 4];
    __shared__ float Bs[NH];
    int tid = threadIdx.x;
    for (int i = tid; i < FIN * NH / 4; i += blockDim.x) Ms[i] = ((const float4*)d_M)[i];
    if (tid < NH) Bs[tid] = d_bvec[tid];
    __syncthreads();

    int n = blockIdx.x * blockDim.x + tid;
    if (n < NG * NH) d_pooled[n] = 0.f;
    if (n >= NN) return;

    float acc[NH];
#pragma unroll
    for (int k = 0; k < NH; k++) acc[k] = 0.f;

    const float4* xr = (const float4*)(x + (size_t)n * FIN);
#pragma unroll
    for (int i4 = 0; i4 < FIN / 4; i4++) {
        float4 xv = __ldg(&xr[i4]);
        float xs[4] = {xv.x, xv.y, xv.z, xv.w};
#pragma unroll
        for (int j = 0; j < 4; j++) {
            float xi = xs[j];
            int i = i4 * 4 + j;
#pragma unroll
            for (int k4 = 0; k4 < NH / 4; k4++) {
                float4 m = Ms[i * (NH / 4) + k4];
                acc[k4 * 4 + 0] = fmaf(xi, m.x, acc[k4 * 4 + 0]);
                acc[k4 * 4 + 1] = fmaf(xi, m.y, acc[k4 * 4 + 1]);
                acc[k4 * 4 + 2] = fmaf(xi, m.z, acc[k4 * 4 + 2]);
                acc[k4 * 4 + 3] = fmaf(xi, m.w, acc[k4 * 4 + 3]);
            }
        }
    }
    float deg = d_dinv[n];
    float di = (deg > 0.f) ? rsqrtf(deg) : 0.f;
    d_dinv[n] = di;
    float4* go = (float4*)(d_g + (size_t)n * NH);
    float4* ao = (float4*)(d_acc + (size_t)n * NH);
#pragma unroll
    for (int k4 = 0; k4 < NH / 4; k4++) {
        float4 o;
        o.x = di * (acc[k4 * 4 + 0] + Bs[k4 * 4 + 0]);
        o.y = di * (acc[k4 * 4 + 1] + Bs[k4 * 4 + 1]);
        o.z = di * (acc[k4 * 4 + 2] + Bs[k4 * 4 + 2]);
        o.w = di * (acc[k4 * 4 + 3] + Bs[k4 * 4 + 3]);
        go[k4] = o;
        ao[k4] = make_float4(0.f, 0.f, 0.f, 0.f);
    }
}

// ---- hot loop: 8 threads per edge, float4 gather + red.global.add.v4.f32 ----
__global__ void k_edge(const int* __restrict__ ei) {
    int tid = blockIdx.x * blockDim.x + threadIdx.x;
    int quad = tid & 7;             // which float4 of the 32-feature row
    int eidx = tid >> 3;
    int estride = (gridDim.x * blockDim.x) >> 3;
    float s0 = d_sp[0], s1 = d_sp[1], s2 = d_sp[2];
    for (int e = eidx; e < NE; e += estride) {
        int r = __ldg(&ei[e]);
        int c = __ldg(&ei[NE + e]);
        unsigned char cd = __ldg(&d_code[e]);
        float w = cd == 0 ? s0 : (cd == 1 ? s1 : s2);
        float4 gv = __ldg((const float4*)(d_g + (size_t)r * NH) + quad);
        red_add_v4(d_acc + (size_t)c * NH + quad * 4,
                   w * gv.x, w * gv.y, w * gv.z, w * gv.w);
    }
}

// ---- fixup + relu + segment pool (batch sorted -> register accumulation per warp) ----
#define CHUNK 64
__global__ void k_pool(const int* __restrict__ batch, const float* __restrict__ gcnB) {
    int lane = threadIdx.x & 31;
    int warp = (blockIdx.x * blockDim.x + threadIdx.x) >> 5;
    int start = warp * CHUNK;
    if (start >= NN) return;
    int end = min(start + CHUNK, NN);
    float gb = __ldg(&gcnB[lane]);
    int cur = __ldg(&batch[start]);
    float accr = 0.f;
    for (int n = start; n < end; n++) {
        int b = __ldg(&batch[n]);
        if (b != cur) {
            atomicAdd(&d_pooled[cur * NH + lane], accr);
            accr = 0.f;
            cur = b;
        }
        float a = d_acc[(size_t)n * NH + lane] + d_g[(size_t)n * NH + lane];
        float v = fmaxf(fmaf(d_dinv[n], a, gb), 0.f);
        accr += v;
    }
    atomicAdd(&d_pooled[cur * NH + lane], accr);
}

// ---- head MLP: one thread per graph ----
__global__ void k_final(const float* __restrict__ fc1W, const float* __restrict__ fc1B,
                        const float* __restrict__ outW, const float* __restrict__ outB,
                        float* __restrict__ out) {
    __shared__ float W[NH * NH], b1[NH], wo[NH];
    int tid = threadIdx.x;
    for (int i = tid; i < NH * NH; i += blockDim.x) W[i] = fc1W[i];
    if (tid < NH) { b1[tid] = fc1B[tid]; wo[tid] = outW[tid]; }
    __syncthreads();
    if (tid >= NG) return;

    float p[NH];
    const float4* pr = (const float4*)(d_pooled + tid * NH);
#pragma unroll
    for (int k4 = 0; k4 < NH / 4; k4++) {
        float4 v = pr[k4];
        p[k4 * 4 + 0] = v.x; p[k4 * 4 + 1] = v.y;
        p[k4 * 4 + 2] = v.z; p[k4 * 4 + 3] = v.w;
    }
    float o = outB[0];
#pragma unroll
    for (int j = 0; j < NH; j++) {
        float z = b1[j];
#pragma unroll
        for (int i = 0; i < NH; i++) z = fmaf(p[i], W[i * NH + j], z);
        o = fmaf(fmaxf(z, 0.f), wo[j], o);
    }
    out[tid] = o;
}

extern "C" void kernel_launch(void* const* d_in, const int* in_sizes, int n_in,
                              void* d_out, int out_size) {
    const float* x    = (const float*)d_in[0];
    const int*   ei   = (const int*)d_in[1];
    const int*   bat  = (const int*)d_in[2];
    const int*   km   = (const int*)d_in[3];
    const int*   um   = (const int*)d_in[4];
    const int*   om   = (const int*)d_in[5];
    const float* mw   = (const float*)d_in[6];
    const float* embW = (const float*)d_in[7];
    const float* embB = (const float*)d_in[8];
    const float* gcnW = (const float*)d_in[9];
    const float* gcnB = (const float*)d_in[10];
    const float* fc1W = (const float*)d_in[11];
    const float* fc1B = (const float*)d_in[12];
    const float* outW = (const float*)d_in[13];
    const float* outB = (const float*)d_in[14];
    float* out = (float*)d_out;

    k_prep<<<1, 256>>>(mw, embW, embB, gcnW);
    k_ew<<<(NE + 255) / 256, 256>>>(km, um, om);
    k_deg<<<(NE / 4 + 255) / 256, 256>>>(ei);
    k_g<<<(NN + 255) / 256, 256>>>(x);
    k_edge<<<2368, 256>>>(ei);
    int pool_warps = (NN + CHUNK - 1) / CHUNK;
    k_pool<<<(pool_warps + 7) / 8, 256>>>(bat, gcnB);
    k_final<<<1, 256>>>(fc1W, fc1B, outW, outB, out);
}

// round 3
// speedup vs baseline: 1.2999x; 1.0654x over previous
#include <cuda_runtime.h>

#define NN 100000
#define NE 3000000
#define THIRD (NE/3)
#define NG 256
#define FIN 64
#define NH 32

// ---- scratch (no allocations allowed) ----
__device__ float d_sp[3];
__device__ float d_M[FIN * NH];
__device__ float d_bvec[NH];
__device__ unsigned char d_code[NE];   // 0/1/2 -> which softmax weight
__device__ float d_dinv[NN];           // deg, then rsqrt(deg) in place
__device__ float d_g[NN * NH];         // dinv[n] * hW[n]
__device__ float d_acc[NN * NH];       // edge-sum accumulator (init = g, self-loop)
__device__ float d_pooled[NG * NH];

__device__ __forceinline__ void red_add_v4(float* addr, float a, float b, float c, float d) {
    asm volatile("red.global.add.v4.f32 [%0], {%1,%2,%3,%4};"
                 :: "l"(addr), "f"(a), "f"(b), "f"(c), "f"(d) : "memory");
}

// ---- tiny precompute: softmax(msg_weights), fused matrix M = [gcn_W[0]; emb_W @ gcn_W[1:]], bvec ----
__global__ void k_prep(const float* __restrict__ mw, const float* __restrict__ embW,
                       const float* __restrict__ embB, const float* __restrict__ gcnW) {
    int tid = threadIdx.x;
    if (tid == 0) {
        float m = fmaxf(mw[0], fmaxf(mw[1], mw[2]));
        float e0 = expf(mw[0] - m), e1 = expf(mw[1] - m), e2 = expf(mw[2] - m);
        float inv = 1.0f / (e0 + e1 + e2);
        d_sp[0] = e0 * inv; d_sp[1] = e1 * inv; d_sp[2] = e2 * inv;
    }
    for (int idx = tid; idx < FIN * NH; idx += blockDim.x) {
        int i = idx / NH, k = idx % NH;
        float v;
        if (i == 0) {
            v = gcnW[k];
        } else {
            v = 0.f;
            for (int c = 0; c < 63; c++)
                v += embW[(i - 1) * 63 + c] * gcnW[(1 + c) * NH + k];
        }
        d_M[idx] = v;
    }
    if (tid < NH) {
        float v = 0.f;
        for (int c = 0; c < 63; c++) v += embB[c] * gcnW[(1 + c) * NH + tid];
        d_bvec[tid] = v;
    }
}

// ---- scatter edge codes + init dinv to self-loop weight ----
__global__ void k_ew(const int* __restrict__ km, const int* __restrict__ um,
                     const int* __restrict__ om) {
    int t = blockIdx.x * blockDim.x + threadIdx.x;
    if (t < THIRD)          d_code[__ldg(&km[t])] = 0;
    else if (t < 2 * THIRD) d_code[__ldg(&um[t - THIRD])] = 1;
    else if (t < NE)        d_code[__ldg(&om[t - 2 * THIRD])] = 2;
    if (t < NN) d_dinv[t] = 1.0f;
}

// ---- degree accumulate: 4 edges per thread ----
__global__ void k_deg(const int* __restrict__ ei) {
    int t = blockIdx.x * blockDim.x + threadIdx.x;
    float s0 = d_sp[0], s1 = d_sp[1], s2 = d_sp[2];
    int e0 = t * 4;
    if (e0 + 3 < NE) {
        uchar4 cd = __ldg((const uchar4*)(d_code + e0));
        int4 col = __ldg((const int4*)(ei + NE + e0));
        unsigned char cs[4] = {cd.x, cd.y, cd.z, cd.w};
        int cols[4] = {col.x, col.y, col.z, col.w};
#pragma unroll
        for (int j = 0; j < 4; j++) {
            float w = cs[j] == 0 ? s0 : (cs[j] == 1 ? s1 : s2);
            atomicAdd(&d_dinv[cols[j]], w);
        }
    } else {
        for (int e = e0; e < NE; e++) {
            unsigned char cd = d_code[e];
            float w = cd == 0 ? s0 : (cd == 1 ? s1 : s2);
            atomicAdd(&d_dinv[__ldg(&ei[NE + e])], w);
        }
    }
}

// ---- g[n] = rsqrt(deg)[n] * (x[n] @ M + bvec); 4 threads/node, 8 outputs each.
//      Also finalizes dinv in place, seeds acc = g (self-loop), zeroes pooled. ----
__global__ void k_g(const float* __restrict__ x) {
    __shared__ float Ms[FIN * NH];
    __shared__ float Bs[NH];
    int tid = threadIdx.x;
    for (int i = tid; i < FIN * NH / 4; i += blockDim.x)
        ((float4*)Ms)[i] = ((const float4*)d_M)[i];
    if (tid < NH) Bs[tid] = d_bvec[tid];
    __syncthreads();

    int gt = blockIdx.x * blockDim.x + tid;
    if (gt < NG * NH) d_pooled[gt] = 0.f;

    int oq = gt & 3;            // which 8-output slice
    int n = gt >> 2;            // node
    if (n >= NN) return;

    float acc[8];
#pragma unroll
    for (int k = 0; k < 8; k++) acc[k] = Bs[oq * 8 + k];

    const float4* xr = (const float4*)(x + (size_t)n * FIN);
#pragma unroll
    for (int i4 = 0; i4 < FIN / 4; i4++) {
        float4 xv = __ldg(&xr[i4]);
        float xs[4] = {xv.x, xv.y, xv.z, xv.w};
#pragma unroll
        for (int j = 0; j < 4; j++) {
            float xi = xs[j];
            const float4* mrow = (const float4*)(Ms + (i4 * 4 + j) * NH + oq * 8);
            float4 m0 = mrow[0], m1 = mrow[1];
            acc[0] = fmaf(xi, m0.x, acc[0]);
            acc[1] = fmaf(xi, m0.y, acc[1]);
            acc[2] = fmaf(xi, m0.z, acc[2]);
            acc[3] = fmaf(xi, m0.w, acc[3]);
            acc[4] = fmaf(xi, m1.x, acc[4]);
            acc[5] = fmaf(xi, m1.y, acc[5]);
            acc[6] = fmaf(xi, m1.z, acc[6]);
            acc[7] = fmaf(xi, m1.w, acc[7]);
        }
    }
    float deg = d_dinv[n];                 // whole quad (same warp) reads before any write
    float di = (deg > 0.f) ? rsqrtf(deg) : 0.f;
    if (oq == 0) d_dinv[n] = di;

    float4* go = (float4*)(d_g + (size_t)n * NH + oq * 8);
    float4* ao = (float4*)(d_acc + (size_t)n * NH + oq * 8);
    float4 o0, o1;
    o0.x = di * acc[0]; o0.y = di * acc[1]; o0.z = di * acc[2]; o0.w = di * acc[3];
    o1.x = di * acc[4]; o1.y = di * acc[5]; o1.z = di * acc[6]; o1.w = di * acc[7];
    go[0] = o0; go[1] = o1;
    ao[0] = o0; ao[1] = o1;   // self-loop contribution pre-seeded
}

// ---- hot loop: 8 threads per edge, float4 gather + red.global.add.v4.f32 ----
__global__ void k_edge(const int* __restrict__ ei) {
    int tid = blockIdx.x * blockDim.x + threadIdx.x;
    int quad = tid & 7;             // which float4 of the 32-feature row
    int eidx = tid >> 3;
    int estride = (gridDim.x * blockDim.x) >> 3;
    float s0 = d_sp[0], s1 = d_sp[1], s2 = d_sp[2];
    for (int e = eidx; e < NE; e += estride) {
        int r = __ldg(&ei[e]);
        int c = __ldg(&ei[NE + e]);
        unsigned char cd = __ldg(&d_code[e]);
        float w = cd == 0 ? s0 : (cd == 1 ? s1 : s2);
        float4 gv = __ldg((const float4*)(d_g + (size_t)r * NH) + quad);
        red_add_v4(d_acc + (size_t)c * NH + quad * 4,
                   w * gv.x, w * gv.y, w * gv.z, w * gv.w);
    }
}

// ---- fixup + relu + segment pool (batch sorted -> register accumulation per warp) ----
#define CHUNK 16
__global__ void k_pool(const int* __restrict__ batch, const float* __restrict__ gcnB) {
    int lane = threadIdx.x & 31;
    int warp = (blockIdx.x * blockDim.x + threadIdx.x) >> 5;
    int start = warp * CHUNK;
    if (start >= NN) return;
    int end = min(start + CHUNK, NN);
    float gb = __ldg(&gcnB[lane]);
    int cur = __ldg(&batch[start]);
    float accr = 0.f;
    for (int n = start; n < end; n++) {
        int b = __ldg(&batch[n]);
        if (b != cur) {
            atomicAdd(&d_pooled[cur * NH + lane], accr);
            accr = 0.f;
            cur = b;
        }
        float a = __ldg(&d_acc[(size_t)n * NH + lane]);   // already includes self-loop g
        float v = fmaxf(fmaf(d_dinv[n], a, gb), 0.f);
        accr += v;
    }
    atomicAdd(&d_pooled[cur * NH + lane], accr);
}

// ---- head MLP: one thread per graph ----
__global__ void k_final(const float* __restrict__ fc1W, const float* __restrict__ fc1B,
                        const float* __restrict__ outW, const float* __restrict__ outB,
                        float* __restrict__ out) {
    __shared__ float W[NH * NH], b1[NH], wo[NH];
    int tid = threadIdx.x;
    for (int i = tid; i < NH * NH; i += blockDim.x) W[i] = fc1W[i];
    if (tid < NH) { b1[tid] = fc1B[tid]; wo[tid] = outW[tid]; }
    __syncthreads();
    if (tid >= NG) return;

    float p[NH];
    const float4* pr = (const float4*)(d_pooled + tid * NH);
#pragma unroll
    for (int k4 = 0; k4 < NH / 4; k4++) {
        float4 v = pr[k4];
        p[k4 * 4 + 0] = v.x; p[k4 * 4 + 1] = v.y;
        p[k4 * 4 + 2] = v.z; p[k4 * 4 + 3] = v.w;
    }
    float o = outB[0];
#pragma unroll
    for (int j = 0; j < NH; j++) {
        float z = b1[j];
#pragma unroll
        for (int i = 0; i < NH; i++) z = fmaf(p[i], W[i * NH + j], z);
        o = fmaf(fmaxf(z, 0.f), wo[j], o);
    }
    out[tid] = o;
}

extern "C" void kernel_launch(void* const* d_in, const int* in_sizes, int n_in,
                              void* d_out, int out_size) {
    const float* x    = (const float*)d_in[0];
    const int*   ei   = (const int*)d_in[1];
    const int*   bat  = (const int*)d_in[2];
    const int*   km   = (const int*)d_in[3];
    const int*   um   = (const int*)d_in[4];
    const int*   om   = (const int*)d_in[5];
    const float* mw   = (const float*)d_in[6];
    const float* embW = (const float*)d_in[7];
    const float* embB = (const float*)d_in[8];
    const float* gcnW = (const float*)d_in[9];
    const float* gcnB = (const float*)d_in[10];
    const float* fc1W = (const float*)d_in[11];
    const float* fc1B = (const float*)d_in[12];
    const float* outW = (const float*)d_in[13];
    const float* outB = (const float*)d_in[14];
    float* out = (float*)d_out;

    k_prep<<<1, 256>>>(mw, embW, embB, gcnW);
    k_ew<<<(NE + 255) / 256, 256>>>(km, um, om);
    k_deg<<<(NE / 4 + 255) / 256, 256>>>(ei);
    k_g<<<(NN * 4 + 255) / 256, 256>>>(x);
    k_edge<<<2368, 256>>>(ei);
    int pool_warps = (NN + CHUNK - 1) / CHUNK;
    k_pool<<<(pool_warps + 7) / 8, 256>>>(bat, gcnB);
    k_final<<<1, 256>>>(fc1W, fc1B, outW, outB, out);
}